// round 1
// baseline (speedup 1.0000x reference)
#include <cuda_runtime.h>
#include <math.h>

#define B_     16384
#define T_     5
#define F1_    300
#define F2_    251
#define IN_    551
#define H_     128
#define G4_    512
#define M_     (B_ * T_)          // 81920

// ---------------- scratch (device globals; no dynamic allocation) ------------
__device__ float g_xg[M_ * G4_];          // [81920][512]  input-projected gates (+bias)
__device__ float g_hbuf[B_ * T_ * H_];    // [16384][640]  LSTM outputs, row = [t0 h..][t1 h..]...
__device__ float g_WhhT[H_ * G4_];        // [128][512]    W_hh transposed (k-major)
__device__ float g_W2p[256 * 544];        // [256][544]    W2 padded with zeros in k 531..543

// ---------------- prep: transposes / padding --------------------------------
__global__ void k_prep(const float* __restrict__ Whh, const float* __restrict__ W2)
{
    int idx = blockIdx.x * blockDim.x + threadIdx.x;
    if (idx < H_ * G4_) {
        int k = idx / G4_;
        int g = idx % G4_;
        g_WhhT[idx] = Whh[g * H_ + k];
    } else {
        int i2 = idx - H_ * G4_;
        if (i2 < 256 * 544) {
            int o = i2 / 544, k = i2 % 544;
            g_W2p[i2] = (k < 531) ? W2[o * 531 + k] : 0.f;
        }
    }
}

// ---------------- K1: xg = concat(x1,x2) @ W_ih^T + b_ih + b_hh --------------
// SGEMM M=81920, N=512, K=551. BM=BN=128, BK=8, 256 threads, 8x8 thread tiles.
__global__ __launch_bounds__(256)
void k1_proj(const float* __restrict__ x1, const float* __restrict__ x2,
             const float* __restrict__ Wih,
             const float* __restrict__ bih, const float* __restrict__ bhh)
{
    __shared__ float As[8][128];
    __shared__ float Bs[8][128];

    const int m0 = blockIdx.x * 128;
    const int n0 = blockIdx.y * 128;
    const int tid = threadIdx.x;

    float acc[8][8];
#pragma unroll
    for (int i = 0; i < 8; i++)
#pragma unroll
        for (int j = 0; j < 8; j++) acc[i][j] = 0.f;

    const int lr = tid >> 1;          // 0..127 : row within tile (A: m, B: n)
    const int lk = (tid & 1) * 4;     // 0 or 4

    const int ty = tid >> 4;          // 0..15
    const int tx = tid & 15;          // 0..15

    for (int k0 = 0; k0 < IN_; k0 += 8) {
        // load A tile (concat-aware) -> As[k][m]
        {
            const int m = m0 + lr;
#pragma unroll
            for (int i = 0; i < 4; i++) {
                int k = k0 + lk + i;
                float v = 0.f;
                if (k < F1_)      v = x1[m * F1_ + k];
                else if (k < IN_) v = x2[m * F2_ + (k - F1_)];
                As[lk + i][lr] = v;
            }
        }
        // load B tile: Bs[k][n] = Wih[n][k]
        {
            const int n = n0 + lr;
#pragma unroll
            for (int i = 0; i < 4; i++) {
                int k = k0 + lk + i;
                Bs[lk + i][lr] = (k < IN_) ? Wih[n * IN_ + k] : 0.f;
            }
        }
        __syncthreads();

#pragma unroll
        for (int kk = 0; kk < 8; kk++) {
            float4 a0 = *(const float4*)&As[kk][ty * 8];
            float4 a1 = *(const float4*)&As[kk][ty * 8 + 4];
            float4 b0 = *(const float4*)&Bs[kk][tx * 8];
            float4 b1 = *(const float4*)&Bs[kk][tx * 8 + 4];
            float a[8] = {a0.x, a0.y, a0.z, a0.w, a1.x, a1.y, a1.z, a1.w};
            float b[8] = {b0.x, b0.y, b0.z, b0.w, b1.x, b1.y, b1.z, b1.w};
#pragma unroll
            for (int i = 0; i < 8; i++)
#pragma unroll
                for (int j = 0; j < 8; j++) acc[i][j] = fmaf(a[i], b[j], acc[i][j]);
        }
        __syncthreads();
    }

    // epilogue: + (b_ih + b_hh), store
    float bv[8];
#pragma unroll
    for (int j = 0; j < 8; j++) {
        int n = n0 + tx * 8 + j;
        bv[j] = bih[n] + bhh[n];
    }
#pragma unroll
    for (int ri = 0; ri < 8; ri++) {
        int m = m0 + ty * 8 + ri;
        float4 o0 = make_float4(acc[ri][0] + bv[0], acc[ri][1] + bv[1],
                                acc[ri][2] + bv[2], acc[ri][3] + bv[3]);
        float4 o1 = make_float4(acc[ri][4] + bv[4], acc[ri][5] + bv[5],
                                acc[ri][6] + bv[6], acc[ri][7] + bv[7]);
        *(float4*)&g_xg[m * G4_ + n0 + tx * 8]     = o0;
        *(float4*)&g_xg[m * G4_ + n0 + tx * 8 + 4] = o1;
    }
}

__device__ __forceinline__ float sigm(float x) { return 1.f / (1.f + expf(-x)); }

// ---------------- K2: LSTM recurrence ----------------------------------------
// 32 rows/block, 256 threads. Per step: g = xg[t] + h @ WhhT  (M=32,N=512,K=128),
// then gate nonlinearity; h kept transposed in SMEM as hT[k][r].
__global__ __launch_bounds__(256, 2)
void k2_lstm()
{
    extern __shared__ float sm2[];
    float* hT   = sm2;              // [128][32]
    float* gbuf = sm2 + 128 * 32;   // [32][512]

    const int tid = threadIdx.x;
    const int rb  = blockIdx.x * 32;

    const int tx = tid & 63;        // gate column group: g0 = tx*8
    const int ty = tid >> 6;        // row group: rows ty*8 .. ty*8+7
    const int g0 = tx * 8;

    // pointwise assignment (fixed across steps so c can stay in registers)
    const int pr  = tid >> 3;           // 0..31  (row)
    const int pj0 = (tid & 7) * 16;     // 0..112 (h index base, 16 each)

    float c[16];
#pragma unroll
    for (int i = 0; i < 16; i++) c[i] = 0.f;

    for (int t = 0; t < T_; t++) {
        float acc[8][8];
        // init accumulators from xg (already includes both biases)
#pragma unroll
        for (int ri = 0; ri < 8; ri++) {
            int m = (rb + ty * 8 + ri) * T_ + t;
            float4 v0 = *(const float4*)&g_xg[m * G4_ + g0];
            float4 v1 = *(const float4*)&g_xg[m * G4_ + g0 + 4];
            acc[ri][0] = v0.x; acc[ri][1] = v0.y; acc[ri][2] = v0.z; acc[ri][3] = v0.w;
            acc[ri][4] = v1.x; acc[ri][5] = v1.y; acc[ri][6] = v1.z; acc[ri][7] = v1.w;
        }

        if (t > 0) {
#pragma unroll 2
            for (int k = 0; k < H_; k++) {
                float4 w0 = *(const float4*)&g_WhhT[k * G4_ + g0];
                float4 w1 = *(const float4*)&g_WhhT[k * G4_ + g0 + 4];
                float4 a0 = *(const float4*)&hT[k * 32 + ty * 8];
                float4 a1 = *(const float4*)&hT[k * 32 + ty * 8 + 4];
                float w[8] = {w0.x, w0.y, w0.z, w0.w, w1.x, w1.y, w1.z, w1.w};
                float a[8] = {a0.x, a0.y, a0.z, a0.w, a1.x, a1.y, a1.z, a1.w};
#pragma unroll
                for (int i = 0; i < 8; i++)
#pragma unroll
                    for (int j = 0; j < 8; j++) acc[i][j] = fmaf(a[i], w[j], acc[i][j]);
            }
        }

        // write gates to smem
#pragma unroll
        for (int ri = 0; ri < 8; ri++) {
            float4 o0 = make_float4(acc[ri][0], acc[ri][1], acc[ri][2], acc[ri][3]);
            float4 o1 = make_float4(acc[ri][4], acc[ri][5], acc[ri][6], acc[ri][7]);
            *(float4*)&gbuf[(ty * 8 + ri) * G4_ + g0]     = o0;
            *(float4*)&gbuf[(ty * 8 + ri) * G4_ + g0 + 4] = o1;
        }
        __syncthreads();

        // pointwise gates: PyTorch order i,f,g,o
#pragma unroll
        for (int jj = 0; jj < 16; jj++) {
            int j = pj0 + jj;
            float gi = gbuf[pr * G4_ + j];
            float gf = gbuf[pr * G4_ + 128 + j];
            float gg = gbuf[pr * G4_ + 256 + j];
            float go = gbuf[pr * G4_ + 384 + j];
            float cn = sigm(gf) * c[jj] + sigm(gi) * tanhf(gg);
            c[jj] = cn;
            float h = sigm(go) * tanhf(cn);
            hT[j * 32 + pr] = h;
            g_hbuf[(rb + pr) * (T_ * H_) + t * H_ + j] = h;
        }
        __syncthreads();
    }
}

// ---------------- K3: MLP 640->531->256->64->2 + softmax ---------------------
// 32 rows/block, 256 threads (8 warps). Warp-cooperative dot products:
// one task = 1 output x 8 rows, lanes split k with float4 loads, shfl reduce.
__global__ __launch_bounds__(256, 1)
void k3_mlp(const float* __restrict__ W1, const float* __restrict__ b1,
            const float* __restrict__ b2,
            const float* __restrict__ W3, const float* __restrict__ b3,
            const float* __restrict__ W4, const float* __restrict__ b4,
            float* __restrict__ out)
{
    extern __shared__ float sm3[];
    float* a0 = sm3;                 // [32][640]  input (hbuf rows)
    float* a1 = a0 + 32 * 640;       // [32][544]  layer1 out (pad 531..543 = 0)
    float* a2 = a1 + 32 * 544;       // [32][256]
    float* a3 = a2 + 32 * 256;       // [32][64]
    float* lg = a3 + 32 * 64;        // [32][2]

    const int tid = threadIdx.x;
    const int rb  = blockIdx.x * 32;
    const int warp = tid >> 5, lane = tid & 31;

    // load input rows
    {
        const float4* src = (const float4*)(g_hbuf + rb * 640);
        float4* dst = (float4*)a0;
        for (int i = tid; i < 32 * 640 / 4; i += 256) dst[i] = src[i];
    }
    // zero the 13 pad columns of a1 (531..543)
    for (int i = tid; i < 32 * 13; i += 256) {
        int r = i / 13, o = 531 + (i % 13);
        a1[r * 544 + o] = 0.f;
    }
    __syncthreads();

    // ---- layer 1: 640 -> 531 ----
    for (int task = warp; task < 531 * 4; task += 8) {
        int o  = task >> 2;
        int r0 = (task & 3) * 8;
        const float4* wrow = (const float4*)(W1 + o * 640);
        float acc[8];
#pragma unroll
        for (int i = 0; i < 8; i++) acc[i] = 0.f;
#pragma unroll
        for (int kb = 0; kb < 5; kb++) {
            float4 w = wrow[kb * 32 + lane];
#pragma unroll
            for (int ri = 0; ri < 8; ri++) {
                float4 xv = *(const float4*)&a0[(r0 + ri) * 640 + kb * 128 + lane * 4];
                acc[ri] = fmaf(w.x, xv.x, fmaf(w.y, xv.y, fmaf(w.z, xv.z, fmaf(w.w, xv.w, acc[ri]))));
            }
        }
#pragma unroll
        for (int off = 16; off; off >>= 1)
#pragma unroll
            for (int ri = 0; ri < 8; ri++)
                acc[ri] += __shfl_xor_sync(0xffffffffu, acc[ri], off);
        if (lane < 8) a1[(r0 + lane) * 544 + o] = fmaxf(acc[lane] + b1[o], 0.f);
    }
    __syncthreads();

    // ---- layer 2: 544(padded 531) -> 256 ----
    for (int task = warp; task < 256 * 4; task += 8) {
        int o  = task >> 2;
        int r0 = (task & 3) * 8;
        float acc[8];
#pragma unroll
        for (int i = 0; i < 8; i++) acc[i] = 0.f;
#pragma unroll
        for (int kb = 0; kb < 5; kb++) {
            int kk = kb * 128 + lane * 4;
            if (kk < 544) {
                float4 w = *(const float4*)&g_W2p[o * 544 + kk];
#pragma unroll
                for (int ri = 0; ri < 8; ri++) {
                    float4 xv = *(const float4*)&a1[(r0 + ri) * 544 + kk];
                    acc[ri] = fmaf(w.x, xv.x, fmaf(w.y, xv.y, fmaf(w.z, xv.z, fmaf(w.w, xv.w, acc[ri]))));
                }
            }
        }
#pragma unroll
        for (int off = 16; off; off >>= 1)
#pragma unroll
            for (int ri = 0; ri < 8; ri++)
                acc[ri] += __shfl_xor_sync(0xffffffffu, acc[ri], off);
        if (lane < 8) a2[(r0 + lane) * 256 + o] = fmaxf(acc[lane] + b2[o], 0.f);
    }
    __syncthreads();

    // ---- layer 3: 256 -> 64 ----
    for (int task = warp; task < 64 * 4; task += 8) {
        int o  = task >> 2;
        int r0 = (task & 3) * 8;
        const float4* wrow = (const float4*)(W3 + o * 256);
        float acc[8];
#pragma unroll
        for (int i = 0; i < 8; i++) acc[i] = 0.f;
#pragma unroll
        for (int kb = 0; kb < 2; kb++) {
            float4 w = wrow[kb * 32 + lane];
#pragma unroll
            for (int ri = 0; ri < 8; ri++) {
                float4 xv = *(const float4*)&a2[(r0 + ri) * 256 + kb * 128 + lane * 4];
                acc[ri] = fmaf(w.x, xv.x, fmaf(w.y, xv.y, fmaf(w.z, xv.z, fmaf(w.w, xv.w, acc[ri]))));
            }
        }
#pragma unroll
        for (int off = 16; off; off >>= 1)
#pragma unroll
            for (int ri = 0; ri < 8; ri++)
                acc[ri] += __shfl_xor_sync(0xffffffffu, acc[ri], off);
        if (lane < 8) a3[(r0 + lane) * 64 + o] = fmaxf(acc[lane] + b3[o], 0.f);
    }
    __syncthreads();

    // ---- layer 4: 64 -> 2 ----
    if (tid < 64) {
        int r = tid >> 1, o = tid & 1;
        float s = b4[o];
        const float* xr = &a3[r * 64];
        const float* wr = &W4[o * 64];
#pragma unroll
        for (int k = 0; k < 64; k++) s = fmaf(xr[k], wr[k], s);
        lg[r * 2 + o] = s;
    }
    __syncthreads();

    // ---- softmax over 2 classes ----
    if (tid < 32) {
        float z0 = lg[tid * 2], z1 = lg[tid * 2 + 1];
        float m = fmaxf(z0, z1);
        float e0 = expf(z0 - m), e1 = expf(z1 - m);
        float inv = 1.f / (e0 + e1);
        out[(rb + tid) * 2]     = e0 * inv;
        out[(rb + tid) * 2 + 1] = e1 * inv;
    }
}

// ---------------- launcher ----------------------------------------------------
extern "C" void kernel_launch(void* const* d_in, const int* in_sizes, int n_in,
                              void* d_out, int out_size)
{
    const float* x1   = (const float*)d_in[0];
    const float* x2   = (const float*)d_in[1];
    const float* W_ih = (const float*)d_in[2];
    const float* W_hh = (const float*)d_in[3];
    const float* b_ih = (const float*)d_in[4];
    const float* b_hh = (const float*)d_in[5];
    const float* W1   = (const float*)d_in[6];
    const float* b1   = (const float*)d_in[7];
    const float* W2   = (const float*)d_in[8];
    const float* b2   = (const float*)d_in[9];
    const float* W3   = (const float*)d_in[10];
    const float* b3   = (const float*)d_in[11];
    const float* W4   = (const float*)d_in[12];
    const float* b4   = (const float*)d_in[13];
    float* out = (float*)d_out;

    // dynamic smem > 48KB requires opt-in (idempotent; safe during capture)
    static_assert(sizeof(float) == 4, "");
    cudaFuncSetAttribute(k2_lstm, cudaFuncAttributeMaxDynamicSharedMemorySize,
                         (128 * 32 + 32 * 512) * 4);
    cudaFuncSetAttribute(k3_mlp, cudaFuncAttributeMaxDynamicSharedMemorySize,
                         (32 * 640 + 32 * 544 + 32 * 256 + 32 * 64 + 64) * 4);

    // prep: transpose W_hh, pad W2
    {
        int total = H_ * G4_ + 256 * 544;
        k_prep<<<(total + 255) / 256, 256>>>(W_hh, W2);
    }
    // input projection GEMM
    {
        dim3 grid(M_ / 128, G4_ / 128);
        k1_proj<<<grid, 256>>>(x1, x2, W_ih, b_ih, b_hh);
    }
    // LSTM recurrence
    k2_lstm<<<B_ / 32, 256, (128 * 32 + 32 * 512) * 4>>>();
    // MLP + softmax
    k3_mlp<<<B_ / 32, 256, (32 * 640 + 32 * 544 + 32 * 256 + 32 * 64 + 64) * 4>>>(
        W1, b1, b2, W3, b3, W4, b4, out);
}

// round 6
// speedup vs baseline: 2.1399x; 2.1399x over previous
#include <cuda_runtime.h>
#include <cuda_bf16.h>
#include <math.h>
#include <stdint.h>

#define B_     16384
#define T_     5
#define F1_    300
#define F2_    251
#define IN_    551
#define H_     128
#define G4_    512
#define M_     (B_ * T_)          // 81920

// ---------------- scratch (device globals; no dynamic allocation) ------------
// NOTE: these are ONLY referenced from device code. Passing a __device__
// symbol as a kernel argument from host code silently passes the HOST shadow
// address (no fault on GB300 due to ATS) — that was the rounds-2..5 bug.
__device__ float g_xg[M_ * G4_];          // [81920][512]
__device__ float g_hbuf[B_ * T_ * H_];    // [16384][640]
__device__ float g_WhhT[H_ * G4_];        // [128][512]
__device__ float g_a1[B_ * 544];          // [16384][544] (pad cols zeroed)
__device__ float g_a2[B_ * 256];          // [16384][256]

// ---------------- prep: W_hh transpose ---------------------------------------
__global__ void k_prep(const float* __restrict__ Whh)
{
    int idx = blockIdx.x * blockDim.x + threadIdx.x;
    if (idx < H_ * G4_) {
        int k = idx / G4_;
        int g = idx % G4_;
        g_WhhT[idx] = Whh[g * H_ + k];
    }
}

// ---------------- double-bf16 tensor-core GEMM --------------------------------
// C[M,N] = A[M,K] @ B[N,K]^T (+bias, relu opt). v = hi + lo (bf16 each);
// acc += hi*hi + hi*lo + lo*hi. fp32 accumulate.
// Block 128x128, k-tile 32. 8 warps: 4(m) x 2(n); warp tile 32x64.
// mma.sync.m16n8k16.bf16. Fragments via conflict-free LDS.32 (stride 40 bf16).
// ASEL: 0 = external A (arg), 1 = g_hbuf, 2 = g_a1
// CSEL: 0 = g_xg, 1 = g_a1, 2 = g_a2

__device__ __forceinline__ void mma_bf16(float* c, const uint32_t* a, const uint32_t* b) {
    asm volatile(
        "mma.sync.aligned.m16n8k16.row.col.f32.bf16.bf16.f32 "
        "{%0,%1,%2,%3}, {%4,%5,%6,%7}, {%8,%9}, {%0,%1,%2,%3};"
        : "+f"(c[0]), "+f"(c[1]), "+f"(c[2]), "+f"(c[3])
        : "r"(a[0]), "r"(a[1]), "r"(a[2]), "r"(a[3]), "r"(b[0]), "r"(b[1]));
}

#define KTILE  32
#define SMK    40                       // row stride in bf16 elems (80B): conflict-free
#define TILE_E (128 * SMK)              // bf16 elems per tile

template<int AMODE, int ASEL, int CSEL, bool RELU, bool DUALBIAS>
__global__ __launch_bounds__(256, 2)
void gemm_bf16x3(const float* __restrict__ Aext, const float* __restrict__ A2, int lda,
                 int Kreal, int KT,
                 const float* __restrict__ Bw, int ldb, int Nreal,
                 const float* __restrict__ bias1, const float* __restrict__ bias2,
                 int ldc, int Nstore)
{
    // device-side global selection (the host must never touch these symbols)
    const float* A = (ASEL == 1) ? (const float*)g_hbuf
                   : (ASEL == 2) ? (const float*)g_a1
                                 : Aext;
    float* C = (CSEL == 0) ? g_xg : (CSEL == 1) ? g_a1 : g_a2;

    extern __shared__ __align__(16) __nv_bfloat16 smb[];
    __nv_bfloat16* AsH = smb;                 // [128][40]
    __nv_bfloat16* AsL = smb + TILE_E;
    __nv_bfloat16* BsH = smb + 2 * TILE_E;
    __nv_bfloat16* BsL = smb + 3 * TILE_E;

    const int tid  = threadIdx.x;
    const int m0   = blockIdx.x * 128;
    const int n0   = blockIdx.y * 128;
    const int lane = tid & 31;
    const int warp = tid >> 5;
    const int wm   = warp & 3;          // m offset wm*32
    const int wn   = warp >> 2;         // n offset wn*64
    const int g    = lane >> 2;
    const int tig  = lane & 3;

    float acc[2][8][4];
#pragma unroll
    for (int mt = 0; mt < 2; mt++)
#pragma unroll
        for (int nt = 0; nt < 8; nt++)
#pragma unroll
            for (int i = 0; i < 4; i++) acc[mt][nt][i] = 0.f;

    const int lrow = tid >> 3;          // 0..31
    const int lcol = (tid & 7) * 4;     // 0,4,...,28

    for (int kt = 0; kt < KT; kt++) {
        const int kb = kt * KTILE + lcol;

        // ---- load A tile (hi/lo bf16 split) ----
#pragma unroll
        for (int it = 0; it < 4; it++) {
            int ml = lrow + it * 32;
            int m  = m0 + ml;
#pragma unroll
            for (int j = 0; j < 4; j++) {
                int kg = kb + j;
                float v = 0.f;
                if (AMODE == 1) {
                    if (kg < F1_)       v = A[m * F1_ + kg];
                    else if (kg < IN_)  v = A2[m * F2_ + (kg - F1_)];
                } else {
                    if (kg < Kreal)     v = A[m * lda + kg];
                }
                __nv_bfloat16 hi = __float2bfloat16_rn(v);
                __nv_bfloat16 lo = __float2bfloat16_rn(v - __bfloat162float(hi));
                AsH[ml * SMK + lcol + j] = hi;
                AsL[ml * SMK + lcol + j] = lo;
            }
        }
        // ---- load B tile (hi/lo bf16 split): Bs[n][k] = Bw[n][k] ----
#pragma unroll
        for (int it = 0; it < 4; it++) {
            int nl = lrow + it * 32;
            int n  = n0 + nl;
#pragma unroll
            for (int j = 0; j < 4; j++) {
                int kg = kb + j;
                float v = 0.f;
                if (n < Nreal && kg < Kreal) v = Bw[n * ldb + kg];
                __nv_bfloat16 hi = __float2bfloat16_rn(v);
                __nv_bfloat16 lo = __float2bfloat16_rn(v - __bfloat162float(hi));
                BsH[nl * SMK + lcol + j] = hi;
                BsL[nl * SMK + lcol + j] = lo;
            }
        }
        __syncthreads();

#pragma unroll
        for (int s = 0; s < KTILE / 16; s++) {
            uint32_t aH[2][4], aL[2][4];
#pragma unroll
            for (int mt = 0; mt < 2; mt++) {
                int r0 = (wm * 32 + mt * 16 + g) * SMK + s * 16 + 2 * tig;
                int r1 = r0 + 8 * SMK;
                aH[mt][0] = *(const uint32_t*)&AsH[r0];
                aH[mt][1] = *(const uint32_t*)&AsH[r1];
                aH[mt][2] = *(const uint32_t*)&AsH[r0 + 8];
                aH[mt][3] = *(const uint32_t*)&AsH[r1 + 8];
                aL[mt][0] = *(const uint32_t*)&AsL[r0];
                aL[mt][1] = *(const uint32_t*)&AsL[r1];
                aL[mt][2] = *(const uint32_t*)&AsL[r0 + 8];
                aL[mt][3] = *(const uint32_t*)&AsL[r1 + 8];
            }
#pragma unroll
            for (int q = 0; q < 8; q++) {
                int nb = (wn * 64 + q * 8 + g) * SMK + s * 16 + 2 * tig;
                uint32_t bH[2], bL[2];
                bH[0] = *(const uint32_t*)&BsH[nb];
                bH[1] = *(const uint32_t*)&BsH[nb + 8];
                bL[0] = *(const uint32_t*)&BsL[nb];
                bL[1] = *(const uint32_t*)&BsL[nb + 8];
#pragma unroll
                for (int mt = 0; mt < 2; mt++) {
                    float* c = acc[mt][q];
                    mma_bf16(c, aH[mt], bH);   // hi*hi
                    mma_bf16(c, aH[mt], bL);   // hi*lo
                    mma_bf16(c, aL[mt], bH);   // lo*hi
                }
            }
        }
        __syncthreads();
    }

    // ---- epilogue: bias (+relu), zero pad cols, store float2 ----
    float bv0[8], bv1[8];
#pragma unroll
    for (int nt = 0; nt < 8; nt++) {
        int col = n0 + wn * 64 + nt * 8 + tig * 2;
        float x0 = 0.f, x1 = 0.f;
        if (col < Nreal)     { x0 = bias1[col];     if (DUALBIAS) x0 += bias2[col]; }
        if (col + 1 < Nreal) { x1 = bias1[col + 1]; if (DUALBIAS) x1 += bias2[col + 1]; }
        bv0[nt] = x0; bv1[nt] = x1;
    }
#pragma unroll
    for (int mt = 0; mt < 2; mt++) {
#pragma unroll
        for (int i = 0; i < 2; i++) {
            int row = m0 + wm * 32 + mt * 16 + g + i * 8;
#pragma unroll
            for (int nt = 0; nt < 8; nt++) {
                int col = n0 + wn * 64 + nt * 8 + tig * 2;
                if (col < Nstore) {
                    float v0 = acc[mt][nt][i * 2]     + bv0[nt];
                    float v1 = acc[mt][nt][i * 2 + 1] + bv1[nt];
                    if (RELU) { v0 = fmaxf(v0, 0.f); v1 = fmaxf(v1, 0.f); }
                    if (col >= Nreal)     v0 = 0.f;
                    if (col + 1 >= Nreal) v1 = 0.f;
                    *(float2*)&C[row * ldc + col] = make_float2(v0, v1);
                }
            }
        }
    }
}

__device__ __forceinline__ float sigm(float x) { return 1.f / (1.f + expf(-x)); }

// ---------------- K2: LSTM recurrence (fp32; known-good, device-global refs) --
__global__ __launch_bounds__(256, 2)
void k2_lstm()
{
    extern __shared__ float sm2[];
    float* hT   = sm2;              // [128][32]
    float* gbuf = sm2 + 128 * 32;   // [32][512]

    const int tid = threadIdx.x;
    const int rb  = blockIdx.x * 32;

    const int tx = tid & 63;
    const int ty = tid >> 6;
    const int g0 = tx * 8;

    const int pr  = tid >> 3;
    const int pj0 = (tid & 7) * 16;

    float c[16];
#pragma unroll
    for (int i = 0; i < 16; i++) c[i] = 0.f;

    for (int t = 0; t < T_; t++) {
        float acc[8][8];
#pragma unroll
        for (int ri = 0; ri < 8; ri++) {
            int m = (rb + ty * 8 + ri) * T_ + t;
            float4 v0 = *(const float4*)&g_xg[m * G4_ + g0];
            float4 v1 = *(const float4*)&g_xg[m * G4_ + g0 + 4];
            acc[ri][0] = v0.x; acc[ri][1] = v0.y; acc[ri][2] = v0.z; acc[ri][3] = v0.w;
            acc[ri][4] = v1.x; acc[ri][5] = v1.y; acc[ri][6] = v1.z; acc[ri][7] = v1.w;
        }

        if (t > 0) {
#pragma unroll 2
            for (int k = 0; k < H_; k++) {
                float4 w0 = *(const float4*)&g_WhhT[k * G4_ + g0];
                float4 w1 = *(const float4*)&g_WhhT[k * G4_ + g0 + 4];
                float4 a0 = *(const float4*)&hT[k * 32 + ty * 8];
                float4 a1 = *(const float4*)&hT[k * 32 + ty * 8 + 4];
                float w[8] = {w0.x, w0.y, w0.z, w0.w, w1.x, w1.y, w1.z, w1.w};
                float a[8] = {a0.x, a0.y, a0.z, a0.w, a1.x, a1.y, a1.z, a1.w};
#pragma unroll
                for (int i = 0; i < 8; i++)
#pragma unroll
                    for (int j = 0; j < 8; j++) acc[i][j] = fmaf(a[i], w[j], acc[i][j]);
            }
        }

#pragma unroll
        for (int ri = 0; ri < 8; ri++) {
            float4 o0 = make_float4(acc[ri][0], acc[ri][1], acc[ri][2], acc[ri][3]);
            float4 o1 = make_float4(acc[ri][4], acc[ri][5], acc[ri][6], acc[ri][7]);
            *(float4*)&gbuf[(ty * 8 + ri) * G4_ + g0]     = o0;
            *(float4*)&gbuf[(ty * 8 + ri) * G4_ + g0 + 4] = o1;
        }
        __syncthreads();

#pragma unroll
        for (int jj = 0; jj < 16; jj++) {
            int j = pj0 + jj;
            float gi = gbuf[pr * G4_ + j];
            float gf = gbuf[pr * G4_ + 128 + j];
            float gg = gbuf[pr * G4_ + 256 + j];
            float go = gbuf[pr * G4_ + 384 + j];
            float cn = sigm(gf) * c[jj] + sigm(gi) * tanhf(gg);
            c[jj] = cn;
            float h = sigm(go) * tanhf(cn);
            hT[j * 32 + pr] = h;
            g_hbuf[(rb + pr) * (T_ * H_) + t * H_ + j] = h;
        }
        __syncthreads();
    }
}

// ---------------- K tail: layer3 (256->64), layer4 (64->2), softmax ----------
__global__ __launch_bounds__(256)
void k_tail(const float* __restrict__ W3, const float* __restrict__ b3,
            const float* __restrict__ W4, const float* __restrict__ b4,
            float* __restrict__ out)
{
    __shared__ float a2s[32 * 256];
    __shared__ float a3[32 * 64];
    __shared__ float lg[64];

    const int tid = threadIdx.x;
    const int rb  = blockIdx.x * 32;
    const int warp = tid >> 5, lane = tid & 31;

    {
        const float4* src = (const float4*)(g_a2 + rb * 256);
        float4* dst = (float4*)a2s;
        for (int i = tid; i < 32 * 256 / 4; i += 256) dst[i] = src[i];
    }
    __syncthreads();

    for (int task = warp; task < 64 * 4; task += 8) {
        int o  = task >> 2;
        int r0 = (task & 3) * 8;
        const float4* wrow = (const float4*)(W3 + o * 256);
        float acc[8];
#pragma unroll
        for (int i = 0; i < 8; i++) acc[i] = 0.f;
#pragma unroll
        for (int kb = 0; kb < 2; kb++) {
            float4 w = wrow[kb * 32 + lane];
#pragma unroll
            for (int ri = 0; ri < 8; ri++) {
                float4 xv = *(const float4*)&a2s[(r0 + ri) * 256 + kb * 128 + lane * 4];
                acc[ri] = fmaf(w.x, xv.x, fmaf(w.y, xv.y, fmaf(w.z, xv.z, fmaf(w.w, xv.w, acc[ri]))));
            }
        }
#pragma unroll
        for (int off = 16; off; off >>= 1)
#pragma unroll
            for (int ri = 0; ri < 8; ri++)
                acc[ri] += __shfl_xor_sync(0xffffffffu, acc[ri], off);
        if (lane < 8) a3[(r0 + lane) * 64 + o] = fmaxf(acc[lane] + b3[o], 0.f);
    }
    __syncthreads();

    if (tid < 64) {
        int r = tid >> 1, o = tid & 1;
        float s = b4[o];
        const float* xr = &a3[r * 64];
        const float* wr = &W4[o * 64];
#pragma unroll
        for (int k = 0; k < 64; k++) s = fmaf(xr[k], wr[k], s);
        lg[r * 2 + o] = s;
    }
    __syncthreads();

    if (tid < 32) {
        float z0 = lg[tid * 2], z1 = lg[tid * 2 + 1];
        float m = fmaxf(z0, z1);
        float e0 = expf(z0 - m), e1 = expf(z1 - m);
        float inv = 1.f / (e0 + e1);
        out[(rb + tid) * 2]     = e0 * inv;
        out[(rb + tid) * 2 + 1] = e1 * inv;
    }
}

// ---------------- launcher ----------------------------------------------------
extern "C" void kernel_launch(void* const* d_in, const int* in_sizes, int n_in,
                              void* d_out, int out_size)
{
    const float* x1   = (const float*)d_in[0];
    const float* x2   = (const float*)d_in[1];
    const float* W_ih = (const float*)d_in[2];
    const float* W_hh = (const float*)d_in[3];
    const float* b_ih = (const float*)d_in[4];
    const float* b_hh = (const float*)d_in[5];
    const float* W1   = (const float*)d_in[6];
    const float* b1   = (const float*)d_in[7];
    const float* W2   = (const float*)d_in[8];
    const float* b2   = (const float*)d_in[9];
    const float* W3   = (const float*)d_in[10];
    const float* b3   = (const float*)d_in[11];
    const float* W4   = (const float*)d_in[12];
    const float* b4   = (const float*)d_in[13];
    float* out = (float*)d_out;

    const int gemm_smem = 4 * TILE_E * 2;   // 40960 B

    cudaFuncSetAttribute(k2_lstm, cudaFuncAttributeMaxDynamicSharedMemorySize,
                         (128 * 32 + 32 * 512) * 4);

    // prep: transpose W_hh
    k_prep<<<(H_ * G4_ + 255) / 256, 256>>>(W_hh);

    // K1: g_xg = concat(x1,x2) @ W_ih^T + (b_ih + b_hh)   [81920 x 512], K=551
    {
        dim3 grid(M_ / 128, G4_ / 128);
        gemm_bf16x3<1, 0, 0, false, true><<<grid, 256, gemm_smem>>>(
            x1, x2, 0, IN_, (IN_ + KTILE - 1) / KTILE,
            W_ih, IN_, G4_, b_ih, b_hh,
            G4_, G4_);
    }

    // K2: LSTM recurrence (g_xg -> g_hbuf)
    k2_lstm<<<B_ / 32, 256, (128 * 32 + 32 * 512) * 4>>>();

    // L1: g_a1 = relu(g_hbuf @ W1^T + b1)   [16384 x 531->544], K=640
    {
        dim3 grid(B_ / 128, 5);
        gemm_bf16x3<0, 1, 1, true, false><<<grid, 256, gemm_smem>>>(
            nullptr, nullptr, 640, 640, 640 / KTILE,
            W1, 640, 531, b1, nullptr,
            544, 544);
    }

    // L2: g_a2 = relu(g_a1 @ W2^T + b2)   [16384 x 256], K=531
    {
        dim3 grid(B_ / 128, 2);
        gemm_bf16x3<0, 2, 2, true, false><<<grid, 256, gemm_smem>>>(
            nullptr, nullptr, 544, 531, (531 + KTILE - 1) / KTILE,
            W2, 531, 256, b2, nullptr,
            256, 256);
    }

    // tail: layer3 + layer4 + softmax (reads g_a2 internally)
    k_tail<<<B_ / 32, 256>>>(W3, b3, W4, b4, out);
}